// round 15
// baseline (speedup 1.0000x reference)
#include <cuda_runtime.h>
#include <cuda_bf16.h>
#include <cstdint>

// Problem dims
#define BB 4
#define TT 64
#define NN 16
#define MM 8
#define DD 512
#define ROWS (BB * TT * NN * MM)   // 32768 flattened (b,t,n,m) rows
#define TNM  (TT * NN * MM)

// ---------------------------------------------------------------------------
// Scratch (__device__ globals; allocation-free rule)
// ---------------------------------------------------------------------------
__device__ float g_Z[(size_t)ROWS * DD];     // Z = x * (Wq^T Wk)
__device__ float g_V[(size_t)ROWS * DD];
__device__ float g_W[TT * NN * MM * MM];     // softmax weights
__device__ float g_u[DD];                    // Wq^T bk
__device__ float g_v[DD];                    // Wk^T bq
__device__ float g_c;                        // bq . bk

__device__ __align__(16) __nv_bfloat16 g_xh[(size_t)ROWS * DD];
__device__ __align__(16) __nv_bfloat16 g_xl[(size_t)ROWS * DD];
__device__ __align__(16) __nv_bfloat16 g_wh[2 * DD * DD];   // z=0: Gt, z=1: Wv
__device__ __align__(16) __nv_bfloat16 g_wl[2 * DD * DD];

// ---------------------------------------------------------------------------
// Helpers
// ---------------------------------------------------------------------------
__device__ __forceinline__ uint32_t smem_to_u32(const void* smem_ptr) {
    uint32_t addr;
    asm("{ .reg .u64 tmp; cvta.to.shared.u64 tmp, %1; cvt.u32.u64 %0, tmp; }"
        : "=r"(addr) : "l"(smem_ptr));
    return addr;
}

#define SMEM_SWIZZLE_128B(byte_offset) \
    ((byte_offset) ^ (((byte_offset) >> 3) & 0x70))

__device__ __forceinline__ void cp_async16(uint32_t dst, const void* src) {
    asm volatile("cp.async.cg.shared.global [%0], [%1], 16;"
                 :: "r"(dst), "l"(src) : "memory");
}
__device__ __forceinline__ void cp_commit() {
    asm volatile("cp.async.commit_group;" ::: "memory");
}
__device__ __forceinline__ void cp_wait1() {
    asm volatile("cp.async.wait_group 1;" ::: "memory");
}
__device__ __forceinline__ void cp_wait0() {
    asm volatile("cp.async.wait_group 0;" ::: "memory");
}

__device__ __forceinline__ void ldmatrix_x4(
    uint32_t& r0, uint32_t& r1, uint32_t& r2, uint32_t& r3, uint32_t addr)
{
    asm volatile("ldmatrix.sync.aligned.m8n8.x4.shared.b16 {%0,%1,%2,%3}, [%4];"
                 : "=r"(r0), "=r"(r1), "=r"(r2), "=r"(r3) : "r"(addr));
}

__device__ __forceinline__ void mma_16816(
    float& c0, float& c1, float& c2, float& c3,
    uint32_t a0, uint32_t a1, uint32_t a2, uint32_t a3,
    uint32_t b0, uint32_t b1)
{
    asm volatile(
        "mma.sync.aligned.m16n8k16.row.col.f32.bf16.bf16.f32 "
        "{%0,%1,%2,%3}, {%4,%5,%6,%7}, {%8,%9}, {%0,%1,%2,%3};"
        : "+f"(c0), "+f"(c1), "+f"(c2), "+f"(c3)
        : "r"(a0), "r"(a1), "r"(a2), "r"(a3), "r"(b0), "r"(b1));
}

__device__ __forceinline__ uint32_t pack_bf16x2(__nv_bfloat16 a, __nv_bfloat16 b) {
    return (uint32_t)__bfloat16_as_ushort(a) | ((uint32_t)__bfloat16_as_ushort(b) << 16);
}

// ---------------------------------------------------------------------------
// Convert x: fp32 -> bf16 hi/lo split
// ---------------------------------------------------------------------------
__global__ __launch_bounds__(256) void convert_x(const float* __restrict__ x)
{
    size_t i = (size_t)blockIdx.x * 256 + threadIdx.x;
    float4 v = ((const float4*)x)[i];
    __nv_bfloat16 h0 = __float2bfloat16_rn(v.x);
    __nv_bfloat16 h1 = __float2bfloat16_rn(v.y);
    __nv_bfloat16 h2 = __float2bfloat16_rn(v.z);
    __nv_bfloat16 h3 = __float2bfloat16_rn(v.w);
    __nv_bfloat16 l0 = __float2bfloat16_rn(v.x - __bfloat162float(h0));
    __nv_bfloat16 l1 = __float2bfloat16_rn(v.y - __bfloat162float(h1));
    __nv_bfloat16 l2 = __float2bfloat16_rn(v.z - __bfloat162float(h2));
    __nv_bfloat16 l3 = __float2bfloat16_rn(v.w - __bfloat162float(h3));
    ((uint2*)g_xh)[i] = make_uint2(pack_bf16x2(h0, h1), pack_bf16x2(h2, h3));
    ((uint2*)g_xl)[i] = make_uint2(pack_bf16x2(l0, l1), pack_bf16x2(l2, l3));
}

// ---------------------------------------------------------------------------
// prep_w: fused weight prework, one launch, 520 blocks x 256 threads.
//   blocks [0,256):   Gt[j,i] = sum_e Wk[e,j]*Wq[e,i] -> bf16 hi/lo slot 0
//   blocks [256,512): convert Wv -> bf16 hi/lo slot 1
//   blocks [512,520): u/v/c bias precompute
// ---------------------------------------------------------------------------
__global__ __launch_bounds__(256) void prep_w(
    const float* __restrict__ Wq, const float* __restrict__ bq,
    const float* __restrict__ Wk, const float* __restrict__ bk,
    const float* __restrict__ Wv)
{
    __shared__ float Ak[16][36];
    __shared__ float Bk[16][36];
    __shared__ float su[4][64];
    __shared__ float sv[4][64];
    __shared__ float scc[64];

    const int bx  = blockIdx.x;
    const int tid = threadIdx.x;

    if (bx < 256) {
        const int j0 = (bx >> 4) * 32;
        const int i0 = (bx & 15) * 32;
        const int le = tid >> 4;
        const int lc = (tid & 15) * 2;
        const int ty = tid >> 4;
        const int tx = tid & 15;

        float acc[2][2] = {{0.0f, 0.0f}, {0.0f, 0.0f}};

        for (int e0 = 0; e0 < DD; e0 += 16) {
            __syncthreads();
            *(float2*)&Ak[le][lc] = *(const float2*)(Wk + (size_t)(e0 + le) * DD + j0 + lc);
            *(float2*)&Bk[le][lc] = *(const float2*)(Wq + (size_t)(e0 + le) * DD + i0 + lc);
            __syncthreads();
#pragma unroll
            for (int e = 0; e < 16; e++) {
                float a0 = Ak[e][ty * 2], a1 = Ak[e][ty * 2 + 1];
                float b0 = Bk[e][tx * 2], b1 = Bk[e][tx * 2 + 1];
                acc[0][0] = fmaf(a0, b0, acc[0][0]);
                acc[0][1] = fmaf(a0, b1, acc[0][1]);
                acc[1][0] = fmaf(a1, b0, acc[1][0]);
                acc[1][1] = fmaf(a1, b1, acc[1][1]);
            }
        }

#pragma unroll
        for (int a = 0; a < 2; a++) {
            const int j = j0 + ty * 2 + a;
            const size_t off = (size_t)j * DD + i0 + tx * 2;
            __nv_bfloat16 h0 = __float2bfloat16_rn(acc[a][0]);
            __nv_bfloat16 h1 = __float2bfloat16_rn(acc[a][1]);
            __nv_bfloat16 l0 = __float2bfloat16_rn(acc[a][0] - __bfloat162float(h0));
            __nv_bfloat16 l1 = __float2bfloat16_rn(acc[a][1] - __bfloat162float(h1));
            *(uint32_t*)(g_wh + off) = pack_bf16x2(h0, h1);
            *(uint32_t*)(g_wl + off) = pack_bf16x2(l0, l1);
        }
    } else if (bx < 512) {
        size_t base = (size_t)(DD * DD / 4);
        size_t i = (size_t)(bx - 256) * 256 + tid;
        float4 v = ((const float4*)Wv)[i];
        __nv_bfloat16 h0 = __float2bfloat16_rn(v.x);
        __nv_bfloat16 h1 = __float2bfloat16_rn(v.y);
        __nv_bfloat16 h2 = __float2bfloat16_rn(v.z);
        __nv_bfloat16 h3 = __float2bfloat16_rn(v.w);
        __nv_bfloat16 l0 = __float2bfloat16_rn(v.x - __bfloat162float(h0));
        __nv_bfloat16 l1 = __float2bfloat16_rn(v.y - __bfloat162float(h1));
        __nv_bfloat16 l2 = __float2bfloat16_rn(v.z - __bfloat162float(h2));
        __nv_bfloat16 l3 = __float2bfloat16_rn(v.w - __bfloat162float(h3));
        ((uint2*)g_wh)[base + i] = make_uint2(pack_bf16x2(h0, h1), pack_bf16x2(h2, h3));
        ((uint2*)g_wl)[base + i] = make_uint2(pack_bf16x2(l0, l1), pack_bf16x2(l2, l3));
    } else {
        const int blk = bx - 512;
        const int il  = tid & 63;
        const int ec  = tid >> 6;
        const int i   = blk * 64 + il;

        float u = 0.0f, v = 0.0f;
        const int e0 = ec * 128;
#pragma unroll 4
        for (int e = e0; e < e0 + 128; e++) {
            u = fmaf(Wq[(size_t)e * DD + i], bk[e], u);
            v = fmaf(Wk[(size_t)e * DD + i], bq[e], v);
        }
        su[ec][il] = u;
        sv[ec][il] = v;
        __syncthreads();

        if (ec == 0) {
            g_u[i] = su[0][il] + su[1][il] + su[2][il] + su[3][il];
            g_v[i] = sv[0][il] + sv[1][il] + sv[2][il] + sv[3][il];
        }

        if (blk == 0) {
            if (ec == 1) {
                float s = 0.0f;
                for (int j = il; j < DD; j += 64) s = fmaf(bq[j], bk[j], s);
                scc[il] = s;
            }
            __syncthreads();
            if (ec == 0 && il == 0) {
                float s = 0.0f;
#pragma unroll
                for (int j = 0; j < 64; j++) s += scc[j];
                g_c = s;
            }
        }
    }
}

// ---------------------------------------------------------------------------
// Z/V GEMM via mma.sync bf16 (split-fp32), R7 shape + single-sync pipeline.
// grid = (4 n-tiles, 256 m-tiles, 2), 128 threads.
// ---------------------------------------------------------------------------
#define STAGE_BYTES 32768u   // A 16KB + B 16KB
#define SMEM_DYN (3 * STAGE_BYTES + 1024)

__global__ __launch_bounds__(128, 1) void qkv_mma(const float* __restrict__ bv)
{
    extern __shared__ __align__(16) char dsm[];
    const uint32_t raw  = smem_to_u32(dsm);
    const uint32_t base = (raw + 1023u) & ~1023u;

    const int tid  = threadIdx.x;
    const int wid  = tid >> 5;
    const int lane = tid & 31;
    const int wm   = wid & 1;
    const int wn   = wid >> 1;
    const int gid  = lane >> 2;
    const int tig  = lane & 3;

    const int z    = blockIdx.z;       // 0: Z, 1: V
    const int row0 = blockIdx.y * 128;
    const int col0 = blockIdx.x * 128;

    const __nv_bfloat16* whz = g_wh + (size_t)z * (DD * DD);
    const __nv_bfloat16* wlz = g_wl + (size_t)z * (DD * DD);

    uint32_t aAddr[4];
#pragma unroll
    for (int mf = 0; mf < 4; mf++) {
        int r = wm * 64 + mf * 16 + (lane & 15);
        uint32_t t = (uint32_t)((lane >> 4) * 16);
        aAddr[mf] = base + r * 128 + (t ^ ((uint32_t)(r & 7) * 16));
    }
    uint32_t bAddr[4];
#pragma unroll
    for (int bh = 0; bh < 4; bh++) {
        int n = wn * 64 + bh * 16 + (lane & 7) + ((lane >> 4) & 1) * 8;
        uint32_t t = (uint32_t)(((lane >> 3) & 1) * 16);
        bAddr[bh] = base + 16384u + n * 128 + (t ^ ((uint32_t)(n & 7) * 16));
    }

    float c[4][8][4];
#pragma unroll
    for (int mf = 0; mf < 4; mf++)
#pragma unroll
        for (int nf = 0; nf < 8; nf++)
#pragma unroll
            for (int q = 0; q < 4; q++) c[mf][nf][q] = 0.0f;

    auto issue_chunk = [&](int ci, int s) {
        const __nv_bfloat16* Asrc = (ci < 16) ? g_xh : g_xl;
        const __nv_bfloat16* Bsrc = (ci >= 8 && ci < 16) ? wlz : whz;
        const int koff = (ci & 7) * 64;
        const uint32_t stage = base + (uint32_t)s * STAGE_BYTES;
#pragma unroll
        for (int j = 0; j < 8; j++) {
            int idx = tid + j * 128;
            int r = idx >> 3, o = idx & 7;
            uint32_t bo = (uint32_t)(r * 128 + o * 16);
            cp_async16(stage + SMEM_SWIZZLE_128B(bo),
                       Asrc + (size_t)(row0 + r) * DD + koff + o * 8);
        }
#pragma unroll
        for (int j = 0; j < 8; j++) {
            int idx = tid + j * 128;
            int n = idx >> 3, o = idx & 7;
            uint32_t bo = (uint32_t)(n * 128 + o * 16);
            cp_async16(stage + 16384u + SMEM_SWIZZLE_128B(bo),
                       Bsrc + (size_t)(col0 + n) * DD + koff + o * 8);
        }
        cp_commit();
    };

    issue_chunk(0, 0);
    issue_chunk(1, 1);

    for (int ck = 0; ck < 24; ck++) {
        if (ck < 23) cp_wait1(); else cp_wait0();
        __syncthreads();
        if (ck + 2 < 24) issue_chunk(ck + 2, (ck + 2) % 3);

        const uint32_t soff = (uint32_t)(ck % 3) * STAGE_BYTES;
#pragma unroll
        for (int kk = 0; kk < 4; kk++) {
            const uint32_t kx = (uint32_t)(kk << 5);
            uint32_t a[4][4];
#pragma unroll
            for (int mf = 0; mf < 4; mf++)
                ldmatrix_x4(a[mf][0], a[mf][1], a[mf][2], a[mf][3],
                            (aAddr[mf] + soff) ^ kx);
            uint32_t b[8][2];
#pragma unroll
            for (int bh = 0; bh < 4; bh++) {
                uint32_t r0, r1, r2, r3;
                ldmatrix_x4(r0, r1, r2, r3, (bAddr[bh] + soff) ^ kx);
                b[bh * 2 + 0][0] = r0; b[bh * 2 + 0][1] = r1;
                b[bh * 2 + 1][0] = r2; b[bh * 2 + 1][1] = r3;
            }
#pragma unroll
            for (int mf = 0; mf < 4; mf++)
#pragma unroll
                for (int nf = 0; nf < 8; nf++)
                    mma_16816(c[mf][nf][0], c[mf][nf][1], c[mf][nf][2], c[mf][nf][3],
                              a[mf][0], a[mf][1], a[mf][2], a[mf][3],
                              b[nf][0], b[nf][1]);
        }
    }

    float* out = (z == 0) ? g_Z : g_V;

#pragma unroll
    for (int nf = 0; nf < 8; nf++) {
        const int col = col0 + wn * 64 + nf * 8 + tig * 2;
        float2 bb = (z == 1) ? *(const float2*)(bv + col) : make_float2(0.0f, 0.0f);
#pragma unroll
        for (int mf = 0; mf < 4; mf++) {
            const int r0 = row0 + wm * 64 + mf * 16 + gid;
            float2 v0 = make_float2(c[mf][nf][0] + bb.x, c[mf][nf][1] + bb.y);
            float2 v1 = make_float2(c[mf][nf][2] + bb.x, c[mf][nf][3] + bb.y);
            *(float2*)(out + (size_t)r0 * DD + col)       = v0;
            *(float2*)(out + (size_t)(r0 + 8) * DD + col) = v1;
        }
    }
}

// ---------------------------------------------------------------------------
// score_softmax v3: cp.async double-buffered chunk pipeline.
// score[m,k] = (Sum_b Sum_d Z[b,m,d]*x[b,k,d] + P[m] + R[k] + 4c) * scale
// Dynamic smem: 2 stages x (Q 16KB + K 16KB) = 64KB. Loop per chunk:
//   wait0 -> sync -> prefetch(ch+1) -> compute(ch).
// One block per (t,n), 256 threads.
// ---------------------------------------------------------------------------
#define SC_STAGE 32768u      // Q 16KB + K 16KB per stage
#define SC_SMEM_DYN (2 * SC_STAGE)

__global__ __launch_bounds__(256) void score_softmax(const float* __restrict__ x)
{
    extern __shared__ __align__(16) char scm[];
    const uint32_t sbase = smem_to_u32(scm);

    __shared__ float part[64 * 65];
    __shared__ float red[4][64];
    __shared__ float Pp[4][8][9];
    __shared__ float Rp[4][8][9];
    __shared__ float PP[8], RR[8];
    __shared__ float sc[64];
    __shared__ float es[64];

    const int tn  = blockIdx.x;
    const int tid = threadIdx.x;
    const int b    = tid >> 6;
    const int r    = tid & 63;
    const int tile = r >> 4;
    const int slc  = r & 15;
    const int mt   = tile >> 1;
    const int kt   = tile & 1;

    const int pb   = tid >> 6;
    const int prow = (tid >> 3) & 7;
    const int ps8  = tid & 7;

    float acc[4][4];
#pragma unroll
    for (int i = 0; i < 4; i++)
#pragma unroll
        for (int j = 0; j < 4; j++) acc[i][j] = 0.0f;
    float pr = 0.0f, rr = 0.0f;

    const float4* Z4 = (const float4*)g_Z;
    const float4* X4 = (const float4*)x;
    const float4* u4 = (const float4*)g_u;
    const float4* v4 = (const float4*)g_v;

    // cp.async loader: chunk ch (128 d-values) into stage s.
    auto load_ch = [&](int ch, int s) {
        const uint32_t qb = sbase + (uint32_t)s * SC_STAGE;
        const uint32_t kb = qb + 16384u;
#pragma unroll
        for (int j = 0; j < 4; j++) {
            int idx = tid + j * 256;
            int lb = idx >> 8, lrr = (idx >> 5) & 7, o = idx & 31;
            size_t grow = (size_t)lb * TNM + (size_t)tn * MM + lrr;
            uint32_t soff = (uint32_t)((lb * 8 + lrr) * 32 + o) * 16u;
            cp_async16(qb + soff, Z4 + grow * (DD / 4) + ch * 32 + o);
            cp_async16(kb + soff, X4 + grow * (DD / 4) + ch * 32 + o);
        }
        cp_commit();
    };

    load_ch(0, 0);

    for (int ch = 0; ch < 4; ch++) {
        cp_wait0();
        __syncthreads();
        if (ch + 1 < 4) load_ch(ch + 1, (ch + 1) & 1);

        const float4* sQ = (const float4*)(scm + (size_t)(ch & 1) * SC_STAGE);
        const float4* sK = (const float4*)(scm + (size_t)(ch & 1) * SC_STAGE + 16384u);

#pragma unroll
        for (int j = 0; j < 2; j++) {
            const int d4 = j * 16 + slc;
            float4 qf[4], kf[4];
#pragma unroll
            for (int i = 0; i < 4; i++)
                qf[i] = sQ[(b * 8 + mt * 4 + i) * 32 + d4];
#pragma unroll
            for (int i = 0; i < 4; i++)
                kf[i] = sK[(b * 8 + kt * 4 + i) * 32 + d4];
#pragma unroll
            for (int i = 0; i < 4; i++)
#pragma unroll
                for (int kx = 0; kx < 4; kx++) {
                    acc[i][kx] = fmaf(qf[i].x, kf[kx].x, acc[i][kx]);
                    acc[i][kx] = fmaf(qf[i].y, kf[kx].y, acc[i][kx]);
                    acc[i][kx] = fmaf(qf[i].z, kf[kx].z, acc[i][kx]);
                    acc[i][kx] = fmaf(qf[i].w, kf[kx].w, acc[i][kx]);
                }
        }

#pragma unroll
        for (int ww = 0; ww < 4; ww++) {
            float4 xv = sK[(pb * 8 + prow) * 32 + ps8 * 4 + ww];
            float4 uu = u4[ch * 32 + ps8 * 4 + ww];
            float4 vv = v4[ch * 32 + ps8 * 4 + ww];
            pr = fmaf(xv.x, uu.x, pr); pr = fmaf(xv.y, uu.y, pr);
            pr = fmaf(xv.z, uu.z, pr); pr = fmaf(xv.w, uu.w, pr);
            rr = fmaf(xv.x, vv.x, rr); rr = fmaf(xv.y, vv.y, rr);
            rr = fmaf(xv.z, vv.z, rr); rr = fmaf(xv.w, vv.w, rr);
        }
        __syncthreads();   // all reads of this stage done before it is refilled
    }

    const int h = b * 16 + slc;
#pragma unroll
    for (int i = 0; i < 4; i++)
#pragma unroll
        for (int kx = 0; kx < 4; kx++) {
            int pair = (mt * 4 + i) * 8 + (kt * 4 + kx);
            part[h * 65 + pair] = acc[i][kx];
        }
    Pp[pb][prow][ps8] = pr;
    Rp[pb][prow][ps8] = rr;
    __syncthreads();

    // Parallel partial reduction: 256 threads, each sums 16 of 64 h-slices.
    {
        const int pair = tid & 63;
        const int q    = tid >> 6;
        float s = 0.0f;
#pragma unroll
        for (int hh = q * 16; hh < q * 16 + 16; hh++) s += part[hh * 65 + pair];
        red[q][pair] = s;
    }
    if (tid < 8) {
        float s = 0.0f;
#pragma unroll
        for (int bb = 0; bb < 4; bb++)
#pragma unroll
            for (int ss = 0; ss < 8; ss++) s += Pp[bb][tid][ss];
        PP[tid] = s;
    } else if (tid < 16) {
        const int m = tid - 8;
        float s = 0.0f;
#pragma unroll
        for (int bb = 0; bb < 4; bb++)
#pragma unroll
            for (int ss = 0; ss < 8; ss++) s += Rp[bb][m][ss];
        RR[m] = s;
    }
    __syncthreads();

    if (tid < 64) {
        float s = red[0][tid] + red[1][tid] + red[2][tid] + red[3][tid];
        const int m = tid >> 3, k = tid & 7;
        sc[tid] = (s + PP[m] + RR[k] + 4.0f * g_c) * 0.04419417382415922f;
    }
    __syncthreads();

    if (tid < 64) {
        const int m = tid >> 3;
        float mx = sc[m * 8];
#pragma unroll
        for (int j = 1; j < 8; j++) mx = fmaxf(mx, sc[m * 8 + j]);
        es[tid] = expf(sc[tid] - mx);
    }
    __syncthreads();

    if (tid < 64) {
        const int m = tid >> 3;
        float sum = 0.0f;
#pragma unroll
        for (int j = 0; j < 8; j++) sum += es[m * 8 + j];
        g_W[tn * 64 + tid] = es[tid] / sum;
    }
}

// ---------------------------------------------------------------------------
// out_kernel: out[b,t,n,m,:] = sum_k w[m,k] * V[b,t,n,k,:]
// One block per (b,t,n), 4096 blocks, 256 threads.
// ---------------------------------------------------------------------------
__global__ __launch_bounds__(256) void out_kernel(float* __restrict__ out)
{
    const int btn = blockIdx.x;
    const int tid = threadIdx.x;
    const int d4  = tid & 127;
    const int mh  = tid >> 7;
    const int tn  = btn % (TT * NN);

    __shared__ float w[64];
    if (tid < 64) w[tid] = g_W[tn * 64 + tid];
    __syncthreads();

    const float4* V4 = (const float4*)(g_V + (size_t)btn * MM * DD);
    float4* O4 = (float4*)(out + (size_t)btn * MM * DD);

    float4 acc[4];
#pragma unroll
    for (int i = 0; i < 4; i++) acc[i] = make_float4(0.f, 0.f, 0.f, 0.f);

#pragma unroll
    for (int k = 0; k < 8; k++) {
        float4 v = V4[k * (DD / 4) + d4];
#pragma unroll
        for (int i = 0; i < 4; i++) {
            float wm = w[(mh * 4 + i) * 8 + k];
            acc[i].x = fmaf(wm, v.x, acc[i].x);
            acc[i].y = fmaf(wm, v.y, acc[i].y);
            acc[i].z = fmaf(wm, v.z, acc[i].z);
            acc[i].w = fmaf(wm, v.w, acc[i].w);
        }
    }

#pragma unroll
    for (int i = 0; i < 4; i++) {
        O4[(mh * 4 + i) * (DD / 4) + d4] = acc[i];
    }
}

// ---------------------------------------------------------------------------
extern "C" void kernel_launch(void* const* d_in, const int* in_sizes, int n_in,
                              void* d_out, int out_size)
{
    const float* x  = (const float*)d_in[0];
    const float* Wq = (const float*)d_in[1];
    const float* bq = (const float*)d_in[2];
    const float* Wk = (const float*)d_in[3];
    const float* bk = (const float*)d_in[4];
    const float* Wv = (const float*)d_in[5];
    const float* bv = (const float*)d_in[6];

    cudaFuncSetAttribute(qkv_mma, cudaFuncAttributeMaxDynamicSharedMemorySize, SMEM_DYN);
    cudaFuncSetAttribute(score_softmax, cudaFuncAttributeMaxDynamicSharedMemorySize, SC_SMEM_DYN);

    convert_x<<<(ROWS * DD / 4) / 256, 256>>>(x);
    prep_w<<<520, 256>>>(Wq, bq, Wk, bk, Wv);
    qkv_mma<<<dim3(4, ROWS / 128, 2), 128, SMEM_DYN>>>(bv);
    score_softmax<<<TT * NN, 256, SC_SMEM_DYN>>>(x);
    out_kernel<<<BB * TT * NN, 256>>>((float*)d_out);
}

// round 16
// speedup vs baseline: 1.0300x; 1.0300x over previous
#include <cuda_runtime.h>
#include <cuda_bf16.h>
#include <cstdint>

// Problem dims
#define BB 4
#define TT 64
#define NN 16
#define MM 8
#define DD 512
#define ROWS (BB * TT * NN * MM)   // 32768 flattened (b,t,n,m) rows
#define TNM  (TT * NN * MM)

// ---------------------------------------------------------------------------
// Scratch (__device__ globals; allocation-free rule)
// ---------------------------------------------------------------------------
__device__ float g_Z[(size_t)ROWS * DD];     // Z = x * (Wq^T Wk)
__device__ float g_V[(size_t)ROWS * DD];
__device__ float g_W[TT * NN * MM * MM];     // softmax weights
__device__ float g_Sp[(size_t)BB * TT * NN * MM * MM];  // per-b partial scores
__device__ float g_u[DD];                    // Wq^T bk
__device__ float g_v[DD];                    // Wk^T bq
__device__ float g_c;                        // bq . bk

__device__ __align__(16) __nv_bfloat16 g_xh[(size_t)ROWS * DD];
__device__ __align__(16) __nv_bfloat16 g_xl[(size_t)ROWS * DD];
__device__ __align__(16) __nv_bfloat16 g_wh[2 * DD * DD];   // z=0: Gt, z=1: Wv
__device__ __align__(16) __nv_bfloat16 g_wl[2 * DD * DD];

// ---------------------------------------------------------------------------
// Helpers
// ---------------------------------------------------------------------------
__device__ __forceinline__ uint32_t smem_to_u32(const void* smem_ptr) {
    uint32_t addr;
    asm("{ .reg .u64 tmp; cvta.to.shared.u64 tmp, %1; cvt.u32.u64 %0, tmp; }"
        : "=r"(addr) : "l"(smem_ptr));
    return addr;
}

#define SMEM_SWIZZLE_128B(byte_offset) \
    ((byte_offset) ^ (((byte_offset) >> 3) & 0x70))

__device__ __forceinline__ void cp_async16(uint32_t dst, const void* src) {
    asm volatile("cp.async.cg.shared.global [%0], [%1], 16;"
                 :: "r"(dst), "l"(src) : "memory");
}
__device__ __forceinline__ void cp_commit() {
    asm volatile("cp.async.commit_group;" ::: "memory");
}
__device__ __forceinline__ void cp_wait1() {
    asm volatile("cp.async.wait_group 1;" ::: "memory");
}
__device__ __forceinline__ void cp_wait0() {
    asm volatile("cp.async.wait_group 0;" ::: "memory");
}

__device__ __forceinline__ void ldmatrix_x4(
    uint32_t& r0, uint32_t& r1, uint32_t& r2, uint32_t& r3, uint32_t addr)
{
    asm volatile("ldmatrix.sync.aligned.m8n8.x4.shared.b16 {%0,%1,%2,%3}, [%4];"
                 : "=r"(r0), "=r"(r1), "=r"(r2), "=r"(r3) : "r"(addr));
}

__device__ __forceinline__ void mma_16816(
    float& c0, float& c1, float& c2, float& c3,
    uint32_t a0, uint32_t a1, uint32_t a2, uint32_t a3,
    uint32_t b0, uint32_t b1)
{
    asm volatile(
        "mma.sync.aligned.m16n8k16.row.col.f32.bf16.bf16.f32 "
        "{%0,%1,%2,%3}, {%4,%5,%6,%7}, {%8,%9}, {%0,%1,%2,%3};"
        : "+f"(c0), "+f"(c1), "+f"(c2), "+f"(c3)
        : "r"(a0), "r"(a1), "r"(a2), "r"(a3), "r"(b0), "r"(b1));
}

__device__ __forceinline__ uint32_t pack_bf16x2(__nv_bfloat16 a, __nv_bfloat16 b) {
    return (uint32_t)__bfloat16_as_ushort(a) | ((uint32_t)__bfloat16_as_ushort(b) << 16);
}

// ---------------------------------------------------------------------------
// Convert x: fp32 -> bf16 hi/lo split
// ---------------------------------------------------------------------------
__global__ __launch_bounds__(256) void convert_x(const float* __restrict__ x)
{
    size_t i = (size_t)blockIdx.x * 256 + threadIdx.x;
    float4 v = ((const float4*)x)[i];
    __nv_bfloat16 h0 = __float2bfloat16_rn(v.x);
    __nv_bfloat16 h1 = __float2bfloat16_rn(v.y);
    __nv_bfloat16 h2 = __float2bfloat16_rn(v.z);
    __nv_bfloat16 h3 = __float2bfloat16_rn(v.w);
    __nv_bfloat16 l0 = __float2bfloat16_rn(v.x - __bfloat162float(h0));
    __nv_bfloat16 l1 = __float2bfloat16_rn(v.y - __bfloat162float(h1));
    __nv_bfloat16 l2 = __float2bfloat16_rn(v.z - __bfloat162float(h2));
    __nv_bfloat16 l3 = __float2bfloat16_rn(v.w - __bfloat162float(h3));
    ((uint2*)g_xh)[i] = make_uint2(pack_bf16x2(h0, h1), pack_bf16x2(h2, h3));
    ((uint2*)g_xl)[i] = make_uint2(pack_bf16x2(l0, l1), pack_bf16x2(l2, l3));
}

// ---------------------------------------------------------------------------
// prep_w: fused weight prework, one launch, 520 blocks x 256 threads.
// ---------------------------------------------------------------------------
__global__ __launch_bounds__(256) void prep_w(
    const float* __restrict__ Wq, const float* __restrict__ bq,
    const float* __restrict__ Wk, const float* __restrict__ bk,
    const float* __restrict__ Wv)
{
    __shared__ float Ak[16][36];
    __shared__ float Bk[16][36];
    __shared__ float su[4][64];
    __shared__ float sv[4][64];
    __shared__ float scc[64];

    const int bx  = blockIdx.x;
    const int tid = threadIdx.x;

    if (bx < 256) {
        const int j0 = (bx >> 4) * 32;
        const int i0 = (bx & 15) * 32;
        const int le = tid >> 4;
        const int lc = (tid & 15) * 2;
        const int ty = tid >> 4;
        const int tx = tid & 15;

        float acc[2][2] = {{0.0f, 0.0f}, {0.0f, 0.0f}};

        for (int e0 = 0; e0 < DD; e0 += 16) {
            __syncthreads();
            *(float2*)&Ak[le][lc] = *(const float2*)(Wk + (size_t)(e0 + le) * DD + j0 + lc);
            *(float2*)&Bk[le][lc] = *(const float2*)(Wq + (size_t)(e0 + le) * DD + i0 + lc);
            __syncthreads();
#pragma unroll
            for (int e = 0; e < 16; e++) {
                float a0 = Ak[e][ty * 2], a1 = Ak[e][ty * 2 + 1];
                float b0 = Bk[e][tx * 2], b1 = Bk[e][tx * 2 + 1];
                acc[0][0] = fmaf(a0, b0, acc[0][0]);
                acc[0][1] = fmaf(a0, b1, acc[0][1]);
                acc[1][0] = fmaf(a1, b0, acc[1][0]);
                acc[1][1] = fmaf(a1, b1, acc[1][1]);
            }
        }

#pragma unroll
        for (int a = 0; a < 2; a++) {
            const int j = j0 + ty * 2 + a;
            const size_t off = (size_t)j * DD + i0 + tx * 2;
            __nv_bfloat16 h0 = __float2bfloat16_rn(acc[a][0]);
            __nv_bfloat16 h1 = __float2bfloat16_rn(acc[a][1]);
            __nv_bfloat16 l0 = __float2bfloat16_rn(acc[a][0] - __bfloat162float(h0));
            __nv_bfloat16 l1 = __float2bfloat16_rn(acc[a][1] - __bfloat162float(h1));
            *(uint32_t*)(g_wh + off) = pack_bf16x2(h0, h1);
            *(uint32_t*)(g_wl + off) = pack_bf16x2(l0, l1);
        }
    } else if (bx < 512) {
        size_t base = (size_t)(DD * DD / 4);
        size_t i = (size_t)(bx - 256) * 256 + tid;
        float4 v = ((const float4*)Wv)[i];
        __nv_bfloat16 h0 = __float2bfloat16_rn(v.x);
        __nv_bfloat16 h1 = __float2bfloat16_rn(v.y);
        __nv_bfloat16 h2 = __float2bfloat16_rn(v.z);
        __nv_bfloat16 h3 = __float2bfloat16_rn(v.w);
        __nv_bfloat16 l0 = __float2bfloat16_rn(v.x - __bfloat162float(h0));
        __nv_bfloat16 l1 = __float2bfloat16_rn(v.y - __bfloat162float(h1));
        __nv_bfloat16 l2 = __float2bfloat16_rn(v.z - __bfloat162float(h2));
        __nv_bfloat16 l3 = __float2bfloat16_rn(v.w - __bfloat162float(h3));
        ((uint2*)g_wh)[base + i] = make_uint2(pack_bf16x2(h0, h1), pack_bf16x2(h2, h3));
        ((uint2*)g_wl)[base + i] = make_uint2(pack_bf16x2(l0, l1), pack_bf16x2(l2, l3));
    } else {
        const int blk = bx - 512;
        const int il  = tid & 63;
        const int ec  = tid >> 6;
        const int i   = blk * 64 + il;

        float u = 0.0f, v = 0.0f;
        const int e0 = ec * 128;
#pragma unroll 4
        for (int e = e0; e < e0 + 128; e++) {
            u = fmaf(Wq[(size_t)e * DD + i], bk[e], u);
            v = fmaf(Wk[(size_t)e * DD + i], bq[e], v);
        }
        su[ec][il] = u;
        sv[ec][il] = v;
        __syncthreads();

        if (ec == 0) {
            g_u[i] = su[0][il] + su[1][il] + su[2][il] + su[3][il];
            g_v[i] = sv[0][il] + sv[1][il] + sv[2][il] + sv[3][il];
        }

        if (blk == 0) {
            if (ec == 1) {
                float s = 0.0f;
                for (int j = il; j < DD; j += 64) s = fmaf(bq[j], bk[j], s);
                scc[il] = s;
            }
            __syncthreads();
            if (ec == 0 && il == 0) {
                float s = 0.0f;
#pragma unroll
                for (int j = 0; j < 64; j++) s += scc[j];
                g_c = s;
            }
        }
    }
}

// ---------------------------------------------------------------------------
// Z/V GEMM via mma.sync bf16 (split-fp32), R7 shape + single-sync pipeline.
// grid = (4 n-tiles, 256 m-tiles, 2), 128 threads.
// ---------------------------------------------------------------------------
#define STAGE_BYTES 32768u   // A 16KB + B 16KB
#define SMEM_DYN (3 * STAGE_BYTES + 1024)

__global__ __launch_bounds__(128, 1) void qkv_mma(const float* __restrict__ bv)
{
    extern __shared__ __align__(16) char dsm[];
    const uint32_t raw  = smem_to_u32(dsm);
    const uint32_t base = (raw + 1023u) & ~1023u;

    const int tid  = threadIdx.x;
    const int wid  = tid >> 5;
    const int lane = tid & 31;
    const int wm   = wid & 1;
    const int wn   = wid >> 1;
    const int gid  = lane >> 2;
    const int tig  = lane & 3;

    const int z    = blockIdx.z;       // 0: Z, 1: V
    const int row0 = blockIdx.y * 128;
    const int col0 = blockIdx.x * 128;

    const __nv_bfloat16* whz = g_wh + (size_t)z * (DD * DD);
    const __nv_bfloat16* wlz = g_wl + (size_t)z * (DD * DD);

    uint32_t aAddr[4];
#pragma unroll
    for (int mf = 0; mf < 4; mf++) {
        int r = wm * 64 + mf * 16 + (lane & 15);
        uint32_t t = (uint32_t)((lane >> 4) * 16);
        aAddr[mf] = base + r * 128 + (t ^ ((uint32_t)(r & 7) * 16));
    }
    uint32_t bAddr[4];
#pragma unroll
    for (int bh = 0; bh < 4; bh++) {
        int n = wn * 64 + bh * 16 + (lane & 7) + ((lane >> 4) & 1) * 8;
        uint32_t t = (uint32_t)(((lane >> 3) & 1) * 16);
        bAddr[bh] = base + 16384u + n * 128 + (t ^ ((uint32_t)(n & 7) * 16));
    }

    float c[4][8][4];
#pragma unroll
    for (int mf = 0; mf < 4; mf++)
#pragma unroll
        for (int nf = 0; nf < 8; nf++)
#pragma unroll
            for (int q = 0; q < 4; q++) c[mf][nf][q] = 0.0f;

    auto issue_chunk = [&](int ci, int s) {
        const __nv_bfloat16* Asrc = (ci < 16) ? g_xh : g_xl;
        const __nv_bfloat16* Bsrc = (ci >= 8 && ci < 16) ? wlz : whz;
        const int koff = (ci & 7) * 64;
        const uint32_t stage = base + (uint32_t)s * STAGE_BYTES;
#pragma unroll
        for (int j = 0; j < 8; j++) {
            int idx = tid + j * 128;
            int r = idx >> 3, o = idx & 7;
            uint32_t bo = (uint32_t)(r * 128 + o * 16);
            cp_async16(stage + SMEM_SWIZZLE_128B(bo),
                       Asrc + (size_t)(row0 + r) * DD + koff + o * 8);
        }
#pragma unroll
        for (int j = 0; j < 8; j++) {
            int idx = tid + j * 128;
            int n = idx >> 3, o = idx & 7;
            uint32_t bo = (uint32_t)(n * 128 + o * 16);
            cp_async16(stage + 16384u + SMEM_SWIZZLE_128B(bo),
                       Bsrc + (size_t)(col0 + n) * DD + koff + o * 8);
        }
        cp_commit();
    };

    issue_chunk(0, 0);
    issue_chunk(1, 1);

    for (int ck = 0; ck < 24; ck++) {
        if (ck < 23) cp_wait1(); else cp_wait0();
        __syncthreads();
        if (ck + 2 < 24) issue_chunk(ck + 2, (ck + 2) % 3);

        const uint32_t soff = (uint32_t)(ck % 3) * STAGE_BYTES;
#pragma unroll
        for (int kk = 0; kk < 4; kk++) {
            const uint32_t kx = (uint32_t)(kk << 5);
            uint32_t a[4][4];
#pragma unroll
            for (int mf = 0; mf < 4; mf++)
                ldmatrix_x4(a[mf][0], a[mf][1], a[mf][2], a[mf][3],
                            (aAddr[mf] + soff) ^ kx);
            uint32_t b[8][2];
#pragma unroll
            for (int bh = 0; bh < 4; bh++) {
                uint32_t r0, r1, r2, r3;
                ldmatrix_x4(r0, r1, r2, r3, (bAddr[bh] + soff) ^ kx);
                b[bh * 2 + 0][0] = r0; b[bh * 2 + 0][1] = r1;
                b[bh * 2 + 1][0] = r2; b[bh * 2 + 1][1] = r3;
            }
#pragma unroll
            for (int mf = 0; mf < 4; mf++)
#pragma unroll
                for (int nf = 0; nf < 8; nf++)
                    mma_16816(c[mf][nf][0], c[mf][nf][1], c[mf][nf][2], c[mf][nf][3],
                              a[mf][0], a[mf][1], a[mf][2], a[mf][3],
                              b[nf][0], b[nf][1]);
        }
    }

    float* out = (z == 0) ? g_Z : g_V;

#pragma unroll
    for (int nf = 0; nf < 8; nf++) {
        const int col = col0 + wn * 64 + nf * 8 + tig * 2;
        float2 bb = (z == 1) ? *(const float2*)(bv + col) : make_float2(0.0f, 0.0f);
#pragma unroll
        for (int mf = 0; mf < 4; mf++) {
            const int r0 = row0 + wm * 64 + mf * 16 + gid;
            float2 v0 = make_float2(c[mf][nf][0] + bb.x, c[mf][nf][1] + bb.y);
            float2 v1 = make_float2(c[mf][nf][2] + bb.x, c[mf][nf][3] + bb.y);
            *(float2*)(out + (size_t)r0 * DD + col)       = v0;
            *(float2*)(out + (size_t)(r0 + 8) * DD + col) = v1;
        }
    }
}

// ---------------------------------------------------------------------------
// score_partial: per-(t,n,b) partial scores.
// sb[m,k] = Sum_d Z[b,m,d]*x[b,k,d] + x[b,m].u + x[b,k].v + c  -> g_Sp
// Grid (1024, 4), 256 threads. One-shot 32KB smem stage, 2x2 register tile.
// ---------------------------------------------------------------------------
__global__ __launch_bounds__(256) void score_partial(const float* __restrict__ x)
{
    __shared__ float4 sZ[1024];       // 8 rows x 128 float4
    __shared__ float4 sX[1024];
    __shared__ float part[16 * 65];   // [slice][pair]
    __shared__ float Ppart[8][17];
    __shared__ float Rpart[8][17];
    __shared__ float PP[8], RR[8];

    const int tn  = blockIdx.x;
    const int b   = blockIdx.y;
    const int tid = threadIdx.x;

    const float4* Z4 = (const float4*)g_Z;
    const float4* X4 = (const float4*)x;
    const float4* u4 = (const float4*)g_u;
    const float4* v4 = (const float4*)g_v;

    // Load 8 Z rows + 8 x rows (batched, high MLP)
#pragma unroll
    for (int j = 0; j < 4; j++) {
        int idx = tid + j * 256;
        int row = idx >> 7, o = idx & 127;
        size_t grow = (size_t)b * TNM + (size_t)tn * MM + row;
        sZ[idx] = Z4[grow * 128 + o];
        sX[idx] = X4[grow * 128 + o];
    }
    __syncthreads();

    // Main dot: tile = tid>>4 (4mt x 4kt of 2x2 pairs), slice = tid&15
    const int tile = tid >> 4;
    const int slc  = tid & 15;
    const int mt   = tile >> 2;
    const int kt   = tile & 3;

    float a00 = 0.f, a01 = 0.f, a10 = 0.f, a11 = 0.f;
#pragma unroll
    for (int w = 0; w < 8; w++) {
        const int d4 = w * 16 + slc;            // strided slice: conflict-free
        float4 z0 = sZ[(mt * 2 + 0) * 128 + d4];
        float4 z1 = sZ[(mt * 2 + 1) * 128 + d4];
        float4 x0 = sX[(kt * 2 + 0) * 128 + d4];
        float4 x1 = sX[(kt * 2 + 1) * 128 + d4];
        a00 = fmaf(z0.x, x0.x, a00); a00 = fmaf(z0.y, x0.y, a00);
        a00 = fmaf(z0.z, x0.z, a00); a00 = fmaf(z0.w, x0.w, a00);
        a01 = fmaf(z0.x, x1.x, a01); a01 = fmaf(z0.y, x1.y, a01);
        a01 = fmaf(z0.z, x1.z, a01); a01 = fmaf(z0.w, x1.w, a01);
        a10 = fmaf(z1.x, x0.x, a10); a10 = fmaf(z1.y, x0.y, a10);
        a10 = fmaf(z1.z, x0.z, a10); a10 = fmaf(z1.w, x0.w, a10);
        a11 = fmaf(z1.x, x1.x, a11); a11 = fmaf(z1.y, x1.y, a11);
        a11 = fmaf(z1.z, x1.z, a11); a11 = fmaf(z1.w, x1.w, a11);
    }
    part[slc * 65 + (mt * 2 + 0) * 8 + kt * 2 + 0] = a00;
    part[slc * 65 + (mt * 2 + 0) * 8 + kt * 2 + 1] = a01;
    part[slc * 65 + (mt * 2 + 1) * 8 + kt * 2 + 0] = a10;
    part[slc * 65 + (mt * 2 + 1) * 8 + kt * 2 + 1] = a11;

    // P/R partials: tid<128 -> P (x.u), tid>=128 -> R (x.v)
    {
        const int lrow = (tid & 127) >> 4;
        const int ls   = tid & 15;
        float s = 0.0f;
        if (tid < 128) {
#pragma unroll
            for (int w = 0; w < 8; w++) {
                const int d4 = w * 16 + ls;
                float4 xv = sX[lrow * 128 + d4];
                float4 uu = u4[d4];
                s = fmaf(xv.x, uu.x, s); s = fmaf(xv.y, uu.y, s);
                s = fmaf(xv.z, uu.z, s); s = fmaf(xv.w, uu.w, s);
            }
            Ppart[lrow][ls] = s;
        } else {
#pragma unroll
            for (int w = 0; w < 8; w++) {
                const int d4 = w * 16 + ls;
                float4 xv = sX[lrow * 128 + d4];
                float4 vv = v4[d4];
                s = fmaf(xv.x, vv.x, s); s = fmaf(xv.y, vv.y, s);
                s = fmaf(xv.z, vv.z, s); s = fmaf(xv.w, vv.w, s);
            }
            Rpart[lrow][ls] = s;
        }
    }
    __syncthreads();

    float sdot = 0.0f;
    if (tid < 64) {
#pragma unroll
        for (int i = 0; i < 16; i++) sdot += part[i * 65 + tid];
    } else if (tid < 72) {
        const int m = tid - 64;
        float s = 0.0f;
#pragma unroll
        for (int i = 0; i < 16; i++) s += Ppart[m][i];
        PP[m] = s;
    } else if (tid < 80) {
        const int m = tid - 72;
        float s = 0.0f;
#pragma unroll
        for (int i = 0; i < 16; i++) s += Rpart[m][i];
        RR[m] = s;
    }
    __syncthreads();

    if (tid < 64) {
        const int m = tid >> 3, k = tid & 7;
        g_Sp[((size_t)b * (TT * NN) + tn) * 64 + tid] = sdot + PP[m] + RR[k] + g_c;
    }
}

// ---------------------------------------------------------------------------
// softmax_k: sum 4 per-b partials, scale, softmax -> g_W.
// Grid 1024 blocks x 64 threads.
// ---------------------------------------------------------------------------
__global__ __launch_bounds__(64) void softmax_k()
{
    __shared__ float sc[64];
    __shared__ float es[64];

    const int tn  = blockIdx.x;
    const int tid = threadIdx.x;

    float s = g_Sp[((size_t)0 * (TT * NN) + tn) * 64 + tid]
            + g_Sp[((size_t)1 * (TT * NN) + tn) * 64 + tid]
            + g_Sp[((size_t)2 * (TT * NN) + tn) * 64 + tid]
            + g_Sp[((size_t)3 * (TT * NN) + tn) * 64 + tid];
    sc[tid] = s * 0.04419417382415922f;   // 1/sqrt(512)
    __syncthreads();

    const int m = tid >> 3;
    float mx = sc[m * 8];
#pragma unroll
    for (int j = 1; j < 8; j++) mx = fmaxf(mx, sc[m * 8 + j]);
    es[tid] = expf(sc[tid] - mx);
    __syncthreads();

    float sum = 0.0f;
#pragma unroll
    for (int j = 0; j < 8; j++) sum += es[m * 8 + j];
    g_W[tn * 64 + tid] = es[tid] / sum;
}

// ---------------------------------------------------------------------------
// out_kernel: out[b,t,n,m,:] = sum_k w[m,k] * V[b,t,n,k,:]
// One block per (b,t,n), 4096 blocks, 256 threads.
// ---------------------------------------------------------------------------
__global__ __launch_bounds__(256) void out_kernel(float* __restrict__ out)
{
    const int btn = blockIdx.x;
    const int tid = threadIdx.x;
    const int d4  = tid & 127;
    const int mh  = tid >> 7;
    const int tn  = btn % (TT * NN);

    __shared__ float w[64];
    if (tid < 64) w[tid] = g_W[tn * 64 + tid];
    __syncthreads();

    const float4* V4 = (const float4*)(g_V + (size_t)btn * MM * DD);
    float4* O4 = (float4*)(out + (size_t)btn * MM * DD);

    float4 acc[4];
#pragma unroll
    for (int i = 0; i < 4; i++) acc[i] = make_float4(0.f, 0.f, 0.f, 0.f);

#pragma unroll
    for (int k = 0; k < 8; k++) {
        float4 v = V4[k * (DD / 4) + d4];
#pragma unroll
        for (int i = 0; i < 4; i++) {
            float wm = w[(mh * 4 + i) * 8 + k];
            acc[i].x = fmaf(wm, v.x, acc[i].x);
            acc[i].y = fmaf(wm, v.y, acc[i].y);
            acc[i].z = fmaf(wm, v.z, acc[i].z);
            acc[i].w = fmaf(wm, v.w, acc[i].w);
        }
    }

#pragma unroll
    for (int i = 0; i < 4; i++) {
        O4[(mh * 4 + i) * (DD / 4) + d4] = acc[i];
    }
}

// ---------------------------------------------------------------------------
extern "C" void kernel_launch(void* const* d_in, const int* in_sizes, int n_in,
                              void* d_out, int out_size)
{
    const float* x  = (const float*)d_in[0];
    const float* Wq = (const float*)d_in[1];
    const float* bq = (const float*)d_in[2];
    const float* Wk = (const float*)d_in[3];
    const float* bk = (const float*)d_in[4];
    const float* Wv = (const float*)d_in[5];
    const float* bv = (const float*)d_in[6];

    cudaFuncSetAttribute(qkv_mma, cudaFuncAttributeMaxDynamicSharedMemorySize, SMEM_DYN);

    convert_x<<<(ROWS * DD / 4) / 256, 256>>>(x);
    prep_w<<<520, 256>>>(Wq, bq, Wk, bk, Wv);
    qkv_mma<<<dim3(4, ROWS / 128, 2), 128, SMEM_DYN>>>(bv);
    score_partial<<<dim3(TT * NN, BB), 256>>>(x);
    softmax_k<<<TT * NN, 64>>>();
    out_kernel<<<BB * TT * NN, 256>>>((float*)d_out);
}

// round 17
// speedup vs baseline: 1.4544x; 1.4120x over previous
#include <cuda_runtime.h>
#include <cuda_bf16.h>
#include <cstdint>

// Problem dims
#define BB 4
#define TT 64
#define NN 16
#define MM 8
#define DD 512
#define ROWS (BB * TT * NN * MM)   // 32768 flattened (b,t,n,m) rows
#define TNM  (TT * NN * MM)

// ---------------------------------------------------------------------------
// Scratch (__device__ globals; allocation-free rule)
// ---------------------------------------------------------------------------
__device__ float g_Z[(size_t)ROWS * DD];     // Z = x * (Wq^T Wk)
__device__ float g_V[(size_t)ROWS * DD];
__device__ float g_W[TT * NN * MM * MM];     // softmax weights
__device__ float g_u[DD];                    // Wq^T bk
__device__ float g_v[DD];                    // Wk^T bq
__device__ float g_c;                        // bq . bk

__device__ __align__(16) __nv_bfloat16 g_xh[(size_t)ROWS * DD];
__device__ __align__(16) __nv_bfloat16 g_xl[(size_t)ROWS * DD];
__device__ __align__(16) __nv_bfloat16 g_wh[2 * DD * DD];   // z=0: Gt, z=1: Wv
__device__ __align__(16) __nv_bfloat16 g_wl[2 * DD * DD];

// ---------------------------------------------------------------------------
// Helpers
// ---------------------------------------------------------------------------
__device__ __forceinline__ uint32_t smem_to_u32(const void* smem_ptr) {
    uint32_t addr;
    asm("{ .reg .u64 tmp; cvta.to.shared.u64 tmp, %1; cvt.u32.u64 %0, tmp; }"
        : "=r"(addr) : "l"(smem_ptr));
    return addr;
}

#define SMEM_SWIZZLE_128B(byte_offset) \
    ((byte_offset) ^ (((byte_offset) >> 3) & 0x70))

__device__ __forceinline__ void cp_async16(uint32_t dst, const void* src) {
    asm volatile("cp.async.cg.shared.global [%0], [%1], 16;"
                 :: "r"(dst), "l"(src) : "memory");
}
__device__ __forceinline__ void cp_commit() {
    asm volatile("cp.async.commit_group;" ::: "memory");
}
__device__ __forceinline__ void cp_wait1() {
    asm volatile("cp.async.wait_group 1;" ::: "memory");
}
__device__ __forceinline__ void cp_wait0() {
    asm volatile("cp.async.wait_group 0;" ::: "memory");
}

__device__ __forceinline__ void ldmatrix_x4(
    uint32_t& r0, uint32_t& r1, uint32_t& r2, uint32_t& r3, uint32_t addr)
{
    asm volatile("ldmatrix.sync.aligned.m8n8.x4.shared.b16 {%0,%1,%2,%3}, [%4];"
                 : "=r"(r0), "=r"(r1), "=r"(r2), "=r"(r3) : "r"(addr));
}

__device__ __forceinline__ void mma_16816(
    float& c0, float& c1, float& c2, float& c3,
    uint32_t a0, uint32_t a1, uint32_t a2, uint32_t a3,
    uint32_t b0, uint32_t b1)
{
    asm volatile(
        "mma.sync.aligned.m16n8k16.row.col.f32.bf16.bf16.f32 "
        "{%0,%1,%2,%3}, {%4,%5,%6,%7}, {%8,%9}, {%0,%1,%2,%3};"
        : "+f"(c0), "+f"(c1), "+f"(c2), "+f"(c3)
        : "r"(a0), "r"(a1), "r"(a2), "r"(a3), "r"(b0), "r"(b1));
}

__device__ __forceinline__ uint32_t pack_bf16x2(__nv_bfloat16 a, __nv_bfloat16 b) {
    return (uint32_t)__bfloat16_as_ushort(a) | ((uint32_t)__bfloat16_as_ushort(b) << 16);
}

// ---------------------------------------------------------------------------
// Convert x: fp32 -> bf16 hi/lo split
// ---------------------------------------------------------------------------
__global__ __launch_bounds__(256) void convert_x(const float* __restrict__ x)
{
    size_t i = (size_t)blockIdx.x * 256 + threadIdx.x;
    float4 v = ((const float4*)x)[i];
    __nv_bfloat16 h0 = __float2bfloat16_rn(v.x);
    __nv_bfloat16 h1 = __float2bfloat16_rn(v.y);
    __nv_bfloat16 h2 = __float2bfloat16_rn(v.z);
    __nv_bfloat16 h3 = __float2bfloat16_rn(v.w);
    __nv_bfloat16 l0 = __float2bfloat16_rn(v.x - __bfloat162float(h0));
    __nv_bfloat16 l1 = __float2bfloat16_rn(v.y - __bfloat162float(h1));
    __nv_bfloat16 l2 = __float2bfloat16_rn(v.z - __bfloat162float(h2));
    __nv_bfloat16 l3 = __float2bfloat16_rn(v.w - __bfloat162float(h3));
    ((uint2*)g_xh)[i] = make_uint2(pack_bf16x2(h0, h1), pack_bf16x2(h2, h3));
    ((uint2*)g_xl)[i] = make_uint2(pack_bf16x2(l0, l1), pack_bf16x2(l2, l3));
}

// ---------------------------------------------------------------------------
// prep_w: fused weight prework, one launch, 520 blocks x 256 threads.
//   blocks [0,256):   Gt[j,i] = sum_e Wk[e,j]*Wq[e,i] -> bf16 hi/lo slot 0
//   blocks [256,512): convert Wv -> bf16 hi/lo slot 1
//   blocks [512,520): u/v/c bias precompute
// ---------------------------------------------------------------------------
__global__ __launch_bounds__(256) void prep_w(
    const float* __restrict__ Wq, const float* __restrict__ bq,
    const float* __restrict__ Wk, const float* __restrict__ bk,
    const float* __restrict__ Wv)
{
    __shared__ float Ak[16][36];
    __shared__ float Bk[16][36];
    __shared__ float su[4][64];
    __shared__ float sv[4][64];
    __shared__ float scc[64];

    const int bx  = blockIdx.x;
    const int tid = threadIdx.x;

    if (bx < 256) {
        const int j0 = (bx >> 4) * 32;
        const int i0 = (bx & 15) * 32;
        const int le = tid >> 4;
        const int lc = (tid & 15) * 2;
        const int ty = tid >> 4;
        const int tx = tid & 15;

        float acc[2][2] = {{0.0f, 0.0f}, {0.0f, 0.0f}};

        for (int e0 = 0; e0 < DD; e0 += 16) {
            __syncthreads();
            *(float2*)&Ak[le][lc] = *(const float2*)(Wk + (size_t)(e0 + le) * DD + j0 + lc);
            *(float2*)&Bk[le][lc] = *(const float2*)(Wq + (size_t)(e0 + le) * DD + i0 + lc);
            __syncthreads();
#pragma unroll
            for (int e = 0; e < 16; e++) {
                float a0 = Ak[e][ty * 2], a1 = Ak[e][ty * 2 + 1];
                float b0 = Bk[e][tx * 2], b1 = Bk[e][tx * 2 + 1];
                acc[0][0] = fmaf(a0, b0, acc[0][0]);
                acc[0][1] = fmaf(a0, b1, acc[0][1]);
                acc[1][0] = fmaf(a1, b0, acc[1][0]);
                acc[1][1] = fmaf(a1, b1, acc[1][1]);
            }
        }

#pragma unroll
        for (int a = 0; a < 2; a++) {
            const int j = j0 + ty * 2 + a;
            const size_t off = (size_t)j * DD + i0 + tx * 2;
            __nv_bfloat16 h0 = __float2bfloat16_rn(acc[a][0]);
            __nv_bfloat16 h1 = __float2bfloat16_rn(acc[a][1]);
            __nv_bfloat16 l0 = __float2bfloat16_rn(acc[a][0] - __bfloat162float(h0));
            __nv_bfloat16 l1 = __float2bfloat16_rn(acc[a][1] - __bfloat162float(h1));
            *(uint32_t*)(g_wh + off) = pack_bf16x2(h0, h1);
            *(uint32_t*)(g_wl + off) = pack_bf16x2(l0, l1);
        }
    } else if (bx < 512) {
        size_t base = (size_t)(DD * DD / 4);
        size_t i = (size_t)(bx - 256) * 256 + tid;
        float4 v = ((const float4*)Wv)[i];
        __nv_bfloat16 h0 = __float2bfloat16_rn(v.x);
        __nv_bfloat16 h1 = __float2bfloat16_rn(v.y);
        __nv_bfloat16 h2 = __float2bfloat16_rn(v.z);
        __nv_bfloat16 h3 = __float2bfloat16_rn(v.w);
        __nv_bfloat16 l0 = __float2bfloat16_rn(v.x - __bfloat162float(h0));
        __nv_bfloat16 l1 = __float2bfloat16_rn(v.y - __bfloat162float(h1));
        __nv_bfloat16 l2 = __float2bfloat16_rn(v.z - __bfloat162float(h2));
        __nv_bfloat16 l3 = __float2bfloat16_rn(v.w - __bfloat162float(h3));
        ((uint2*)g_wh)[base + i] = make_uint2(pack_bf16x2(h0, h1), pack_bf16x2(h2, h3));
        ((uint2*)g_wl)[base + i] = make_uint2(pack_bf16x2(l0, l1), pack_bf16x2(l2, l3));
    } else {
        const int blk = bx - 512;
        const int il  = tid & 63;
        const int ec  = tid >> 6;
        const int i   = blk * 64 + il;

        float u = 0.0f, v = 0.0f;
        const int e0 = ec * 128;
#pragma unroll 4
        for (int e = e0; e < e0 + 128; e++) {
            u = fmaf(Wq[(size_t)e * DD + i], bk[e], u);
            v = fmaf(Wk[(size_t)e * DD + i], bq[e], v);
        }
        su[ec][il] = u;
        sv[ec][il] = v;
        __syncthreads();

        if (ec == 0) {
            g_u[i] = su[0][il] + su[1][il] + su[2][il] + su[3][il];
            g_v[i] = sv[0][il] + sv[1][il] + sv[2][il] + sv[3][il];
        }

        if (blk == 0) {
            if (ec == 1) {
                float s = 0.0f;
                for (int j = il; j < DD; j += 64) s = fmaf(bq[j], bk[j], s);
                scc[il] = s;
            }
            __syncthreads();
            if (ec == 0 && il == 0) {
                float s = 0.0f;
#pragma unroll
                for (int j = 0; j < 64; j++) s += scc[j];
                g_c = s;
            }
        }
    }
}

// ---------------------------------------------------------------------------
// Z/V GEMM via mma.sync bf16 (split-fp32), R7 shape + single-sync pipeline.
// z=0: Z = x*Gt^T (no bias); z=1: V = x*Wv^T + bv.
// CTA 128x128, 4 warps (2m x 2n), warp tile 64x64, 3-stage cp.async.
// grid = (4 n-tiles, 256 m-tiles, 2), 128 threads.
// ---------------------------------------------------------------------------
#define STAGE_BYTES 32768u   // A 16KB + B 16KB
#define SMEM_DYN (3 * STAGE_BYTES + 1024)

__global__ __launch_bounds__(128, 1) void qkv_mma(const float* __restrict__ bv)
{
    extern __shared__ __align__(16) char dsm[];
    const uint32_t raw  = smem_to_u32(dsm);
    const uint32_t base = (raw + 1023u) & ~1023u;

    const int tid  = threadIdx.x;
    const int wid  = tid >> 5;
    const int lane = tid & 31;
    const int wm   = wid & 1;
    const int wn   = wid >> 1;
    const int gid  = lane >> 2;
    const int tig  = lane & 3;

    const int z    = blockIdx.z;       // 0: Z, 1: V
    const int row0 = blockIdx.y * 128;
    const int col0 = blockIdx.x * 128;

    const __nv_bfloat16* whz = g_wh + (size_t)z * (DD * DD);
    const __nv_bfloat16* wlz = g_wl + (size_t)z * (DD * DD);

    uint32_t aAddr[4];
#pragma unroll
    for (int mf = 0; mf < 4; mf++) {
        int r = wm * 64 + mf * 16 + (lane & 15);
        uint32_t t = (uint32_t)((lane >> 4) * 16);
        aAddr[mf] = base + r * 128 + (t ^ ((uint32_t)(r & 7) * 16));
    }
    uint32_t bAddr[4];
#pragma unroll
    for (int bh = 0; bh < 4; bh++) {
        int n = wn * 64 + bh * 16 + (lane & 7) + ((lane >> 4) & 1) * 8;
        uint32_t t = (uint32_t)(((lane >> 3) & 1) * 16);
        bAddr[bh] = base + 16384u + n * 128 + (t ^ ((uint32_t)(n & 7) * 16));
    }

    float c[4][8][4];
#pragma unroll
    for (int mf = 0; mf < 4; mf++)
#pragma unroll
        for (int nf = 0; nf < 8; nf++)
#pragma unroll
            for (int q = 0; q < 4; q++) c[mf][nf][q] = 0.0f;

    auto issue_chunk = [&](int ci, int s) {
        const __nv_bfloat16* Asrc = (ci < 16) ? g_xh : g_xl;
        const __nv_bfloat16* Bsrc = (ci >= 8 && ci < 16) ? wlz : whz;
        const int koff = (ci & 7) * 64;
        const uint32_t stage = base + (uint32_t)s * STAGE_BYTES;
#pragma unroll
        for (int j = 0; j < 8; j++) {
            int idx = tid + j * 128;
            int r = idx >> 3, o = idx & 7;
            uint32_t bo = (uint32_t)(r * 128 + o * 16);
            cp_async16(stage + SMEM_SWIZZLE_128B(bo),
                       Asrc + (size_t)(row0 + r) * DD + koff + o * 8);
        }
#pragma unroll
        for (int j = 0; j < 8; j++) {
            int idx = tid + j * 128;
            int n = idx >> 3, o = idx & 7;
            uint32_t bo = (uint32_t)(n * 128 + o * 16);
            cp_async16(stage + 16384u + SMEM_SWIZZLE_128B(bo),
                       Bsrc + (size_t)(col0 + n) * DD + koff + o * 8);
        }
        cp_commit();
    };

    issue_chunk(0, 0);
    issue_chunk(1, 1);

    for (int ck = 0; ck < 24; ck++) {
        if (ck < 23) cp_wait1(); else cp_wait0();
        __syncthreads();
        if (ck + 2 < 24) issue_chunk(ck + 2, (ck + 2) % 3);

        const uint32_t soff = (uint32_t)(ck % 3) * STAGE_BYTES;
#pragma unroll
        for (int kk = 0; kk < 4; kk++) {
            const uint32_t kx = (uint32_t)(kk << 5);
            uint32_t a[4][4];
#pragma unroll
            for (int mf = 0; mf < 4; mf++)
                ldmatrix_x4(a[mf][0], a[mf][1], a[mf][2], a[mf][3],
                            (aAddr[mf] + soff) ^ kx);
            uint32_t b[8][2];
#pragma unroll
            for (int bh = 0; bh < 4; bh++) {
                uint32_t r0, r1, r2, r3;
                ldmatrix_x4(r0, r1, r2, r3, (bAddr[bh] + soff) ^ kx);
                b[bh * 2 + 0][0] = r0; b[bh * 2 + 0][1] = r1;
                b[bh * 2 + 1][0] = r2; b[bh * 2 + 1][1] = r3;
            }
#pragma unroll
            for (int mf = 0; mf < 4; mf++)
#pragma unroll
                for (int nf = 0; nf < 8; nf++)
                    mma_16816(c[mf][nf][0], c[mf][nf][1], c[mf][nf][2], c[mf][nf][3],
                              a[mf][0], a[mf][1], a[mf][2], a[mf][3],
                              b[nf][0], b[nf][1]);
        }
    }

    float* out = (z == 0) ? g_Z : g_V;

#pragma unroll
    for (int nf = 0; nf < 8; nf++) {
        const int col = col0 + wn * 64 + nf * 8 + tig * 2;
        float2 bb = (z == 1) ? *(const float2*)(bv + col) : make_float2(0.0f, 0.0f);
#pragma unroll
        for (int mf = 0; mf < 4; mf++) {
            const int r0 = row0 + wm * 64 + mf * 16 + gid;
            float2 v0 = make_float2(c[mf][nf][0] + bb.x, c[mf][nf][1] + bb.y);
            float2 v1 = make_float2(c[mf][nf][2] + bb.x, c[mf][nf][3] + bb.y);
            *(float2*)(out + (size_t)r0 * DD + col)       = v0;
            *(float2*)(out + (size_t)(r0 + 8) * DD + col) = v1;
        }
    }
}

// ---------------------------------------------------------------------------
// score_softmax: scores + softmax -> g_W.
// score[m,k] = (Sum_b Sum_d Z[b,m,d]*x[b,k,d] + P[m] + R[k] + 4c) * scale
// One block per (t,n), 256 threads; parallel 256-thread partial reduction.
// ---------------------------------------------------------------------------
__global__ __launch_bounds__(256) void score_softmax(const float* __restrict__ x)
{
    __shared__ float sQ[4096];        // Z rows   [4b][8][128]
    __shared__ float sK[4096];        // x rows   [4b][8][128]
    __shared__ float part[64 * 65];
    __shared__ float red[4][64];
    __shared__ float Pp[4][8][9];
    __shared__ float Rp[4][8][9];
    __shared__ float PP[8], RR[8];
    __shared__ float sc[64];
    __shared__ float es[64];

    const int tn  = blockIdx.x;
    const int tid = threadIdx.x;
    const int b    = tid >> 6;
    const int r    = tid & 63;
    const int tile = r >> 4;
    const int slc  = r & 15;
    const int mt   = tile >> 1;
    const int kt   = tile & 1;

    const int pb   = tid >> 6;
    const int prow = (tid >> 3) & 7;
    const int ps8  = tid & 7;

    float acc[4][4];
#pragma unroll
    for (int i = 0; i < 4; i++)
#pragma unroll
        for (int j = 0; j < 4; j++) acc[i][j] = 0.0f;
    float pr = 0.0f, rr = 0.0f;

    const float4* Z4 = (const float4*)g_Z;
    const float4* X4 = (const float4*)x;
    const float4* u4 = (const float4*)g_u;
    const float4* v4 = (const float4*)g_v;

    for (int ch = 0; ch < 4; ch++) {
        __syncthreads();
#pragma unroll
        for (int j = 0; j < 4; j++) {
            int idx = tid + j * 256;
            int lb = idx >> 8, lrr = (idx >> 5) & 7, o = idx & 31;
            size_t grow = (size_t)lb * TNM + (size_t)tn * MM + lrr;
            ((float4*)sQ)[(lb * 8 + lrr) * 32 + o] = Z4[grow * (DD / 4) + ch * 32 + o];
            ((float4*)sK)[(lb * 8 + lrr) * 32 + o] = X4[grow * (DD / 4) + ch * 32 + o];
        }
        __syncthreads();

#pragma unroll
        for (int j = 0; j < 2; j++) {
            const int d4 = j * 16 + slc;
            float4 qf[4], kf[4];
#pragma unroll
            for (int i = 0; i < 4; i++)
                qf[i] = ((const float4*)sQ)[(b * 8 + mt * 4 + i) * 32 + d4];
#pragma unroll
            for (int i = 0; i < 4; i++)
                kf[i] = ((const float4*)sK)[(b * 8 + kt * 4 + i) * 32 + d4];
#pragma unroll
            for (int i = 0; i < 4; i++)
#pragma unroll
                for (int kx = 0; kx < 4; kx++) {
                    acc[i][kx] = fmaf(qf[i].x, kf[kx].x, acc[i][kx]);
                    acc[i][kx] = fmaf(qf[i].y, kf[kx].y, acc[i][kx]);
                    acc[i][kx] = fmaf(qf[i].z, kf[kx].z, acc[i][kx]);
                    acc[i][kx] = fmaf(qf[i].w, kf[kx].w, acc[i][kx]);
                }
        }

#pragma unroll
        for (int ww = 0; ww < 4; ww++) {
            float4 xv = ((const float4*)sK)[(pb * 8 + prow) * 32 + ps8 * 4 + ww];
            float4 uu = u4[ch * 32 + ps8 * 4 + ww];
            float4 vv = v4[ch * 32 + ps8 * 4 + ww];
            pr = fmaf(xv.x, uu.x, pr); pr = fmaf(xv.y, uu.y, pr);
            pr = fmaf(xv.z, uu.z, pr); pr = fmaf(xv.w, uu.w, pr);
            rr = fmaf(xv.x, vv.x, rr); rr = fmaf(xv.y, vv.y, rr);
            rr = fmaf(xv.z, vv.z, rr); rr = fmaf(xv.w, vv.w, rr);
        }
    }

    const int h = b * 16 + slc;
#pragma unroll
    for (int i = 0; i < 4; i++)
#pragma unroll
        for (int kx = 0; kx < 4; kx++) {
            int pair = (mt * 4 + i) * 8 + (kt * 4 + kx);
            part[h * 65 + pair] = acc[i][kx];
        }
    Pp[pb][prow][ps8] = pr;
    Rp[pb][prow][ps8] = rr;
    __syncthreads();

    // Parallel partial reduction: 256 threads, each sums 16 of 64 h-slices.
    {
        const int pair = tid & 63;
        const int q    = tid >> 6;
        float s = 0.0f;
#pragma unroll
        for (int hh = q * 16; hh < q * 16 + 16; hh++) s += part[hh * 65 + pair];
        red[q][pair] = s;
    }
    if (tid < 8) {
        float s = 0.0f;
#pragma unroll
        for (int bb = 0; bb < 4; bb++)
#pragma unroll
            for (int ss = 0; ss < 8; ss++) s += Pp[bb][tid][ss];
        PP[tid] = s;
    } else if (tid < 16) {
        const int m = tid - 8;
        float s = 0.0f;
#pragma unroll
        for (int bb = 0; bb < 4; bb++)
#pragma unroll
            for (int ss = 0; ss < 8; ss++) s += Rp[bb][m][ss];
        RR[m] = s;
    }
    __syncthreads();

    if (tid < 64) {
        float s = red[0][tid] + red[1][tid] + red[2][tid] + red[3][tid];
        const int m = tid >> 3, k = tid & 7;
        sc[tid] = (s + PP[m] + RR[k] + 4.0f * g_c) * 0.04419417382415922f;
    }
    __syncthreads();

    if (tid < 64) {
        const int m = tid >> 3;
        float mx = sc[m * 8];
#pragma unroll
        for (int j = 1; j < 8; j++) mx = fmaxf(mx, sc[m * 8 + j]);
        es[tid] = expf(sc[tid] - mx);
    }
    __syncthreads();

    if (tid < 64) {
        const int m = tid >> 3;
        float sum = 0.0f;
#pragma unroll
        for (int j = 0; j < 8; j++) sum += es[m * 8 + j];
        g_W[tn * 64 + tid] = es[tid] / sum;
    }
}

// ---------------------------------------------------------------------------
// out_kernel: out[b,t,n,m,:] = sum_k w[m,k] * V[b,t,n,k,:]
// One block per (b,t,n), 4096 blocks, 256 threads.
// ---------------------------------------------------------------------------
__global__ __launch_bounds__(256) void out_kernel(float* __restrict__ out)
{
    const int btn = blockIdx.x;
    const int tid = threadIdx.x;
    const int d4  = tid & 127;
    const int mh  = tid >> 7;
    const int tn  = btn % (TT * NN);

    __shared__ float w[64];
    if (tid < 64) w[tid] = g_W[tn * 64 + tid];
    __syncthreads();

    const float4* V4 = (const float4*)(g_V + (size_t)btn * MM * DD);
    float4* O4 = (float4*)(out + (size_t)btn * MM * DD);

    float4 acc[4];
#pragma unroll
    for (int i = 0; i < 4; i++) acc[i] = make_float4(0.f, 0.f, 0.f, 0.f);

#pragma unroll
    for (int k = 0; k < 8; k++) {
        float4 v = V4[k * (DD / 4) + d4];
#pragma unroll
        for (int i = 0; i < 4; i++) {
            float wm = w[(mh * 4 + i) * 8 + k];
            acc[i].x = fmaf(wm, v.x, acc[i].x);
            acc[i].y = fmaf(wm, v.y, acc[i].y);
            acc[i].z = fmaf(wm, v.z, acc[i].z);
            acc[i].w = fmaf(wm, v.w, acc[i].w);
        }
    }

#pragma unroll
    for (int i = 0; i < 4; i++) {
        O4[(mh * 4 + i) * (DD / 4) + d4] = acc[i];
    }
}

// ---------------------------------------------------------------------------
extern "C" void kernel_launch(void* const* d_in, const int* in_sizes, int n_in,
                              void* d_out, int out_size)
{
    const float* x  = (const float*)d_in[0];
    const float* Wq = (const float*)d_in[1];
    const float* bq = (const float*)d_in[2];
    const float* Wk = (const float*)d_in[3];
    const float* bk = (const float*)d_in[4];
    const float* Wv = (const float*)d_in[5];
    const float* bv = (const float*)d_in[6];

    cudaFuncSetAttribute(qkv_mma, cudaFuncAttributeMaxDynamicSharedMemorySize, SMEM_DYN);

    convert_x<<<(ROWS * DD / 4) / 256, 256>>>(x);
    prep_w<<<520, 256>>>(Wq, bq, Wk, bk, Wv);
    qkv_mma<<<dim3(4, ROWS / 128, 2), 128, SMEM_DYN>>>(bv);
    score_softmax<<<TT * NN, 256>>>(x);
    out_kernel<<<BB * TT * NN, 256>>>((float*)d_out);
}